// round 16
// baseline (speedup 1.0000x reference)
#include <cuda_runtime.h>
#include <cuda_bf16.h>
#include <cstdint>

#define NN 100000
#define EE 1250000
#define DD 64
#define NB ((NN + 255) / 256)   // 391 scan blocks
#define EPAD (EE + 8 * NN)      // padded edge capacity

// ---------------------------------------------------------------------------
// Scratch (__device__ globals; zero-initialized at load; self-restoring)
// ---------------------------------------------------------------------------
__device__ unsigned long long g_pack[NN];  // [63:48] count, [47:0] w*2^40 (cleared by scan1)
__device__ float g_dis[NN];                // deg^{-1/2}
__device__ int   g_fill[NN];               // reorder cursor (= global rowstart after scan3)
__device__ int   g_rowstart[NN];           // padded start (global after scan3)
__device__ int   g_rowend[NN];             // padded end (global after scan3)
__device__ int   g_bsum[NB];               // padded block totals
__device__ __align__(16) int2 g_epair[EPAD]; // (src*256, coef-bits); pad slots stay (0,0)
__device__ float g_h[NN * DD];             // gemm1 output
__device__ float g_h2[NN * DD];            // fused gather1+gemm2 output

// ---------------------------------------------------------------------------
// Histogram: ONE packed u64 atomic per edge (count<<48 | w*2^40).
// ---------------------------------------------------------------------------
__global__ void k_hist(const int* __restrict__ dst, const float* __restrict__ w) {
    int t = blockIdx.x * blockDim.x + threadIdx.x;
    int e = t * 4;
    const float FP = 1099511627776.0f;  // 2^40
    if (e + 4 <= EE) {
        int4 d = *reinterpret_cast<const int4*>(dst + e);
        float4 wv = *reinterpret_cast<const float4*>(w + e);
        atomicAdd(&g_pack[d.x], (1ULL << 48) | (unsigned long long)(wv.x * FP));
        atomicAdd(&g_pack[d.y], (1ULL << 48) | (unsigned long long)(wv.y * FP));
        atomicAdd(&g_pack[d.z], (1ULL << 48) | (unsigned long long)(wv.z * FP));
        atomicAdd(&g_pack[d.w], (1ULL << 48) | (unsigned long long)(wv.w * FP));
    } else {
        for (; e < EE; e++)
            atomicAdd(&g_pack[dst[e]], (1ULL << 48) | (unsigned long long)(w[e] * FP));
    }
}

// ---------------------------------------------------------------------------
// scan1: read+clear pack, compute dis, scan PADDED counts (block-local).
// ---------------------------------------------------------------------------
__global__ void k_scan1() {
    __shared__ int sh[256];
    int t = threadIdx.x;
    int i = blockIdx.x * 256 + t;
    int cntp = 0;
    if (i < NN) {
        unsigned long long p = g_pack[i];
        g_pack[i] = 0ULL;                              // restore for next run
        int cnt = (int)(p >> 48);
        float deg = (float)(p & ((1ULL << 48) - 1ULL)) * (1.0f / 1099511627776.0f);
        g_dis[i] = rsqrtf(deg + 1.0f);
        cntp = (cnt + 7) & ~7;                         // pad to multiple of 8
    }
    sh[t] = cntp;
    __syncthreads();
    for (int off = 1; off < 256; off <<= 1) {
        int u = (t >= off) ? sh[t - off] : 0;
        __syncthreads();
        sh[t] += u;
        __syncthreads();
    }
    if (i < NN) {
        g_rowstart[i] = sh[t] - cntp;                  // local exclusive (mult of 8)
        g_rowend[i]   = sh[t];                         // local inclusive padded
    }
    if (t == 255) g_bsum[blockIdx.x] = sh[255];
}

// scan3 (fused scan2): block-prefix of g_bsum; globalize; prime fill cursor.
__global__ void k_scan3() {
    __shared__ int sh[256];
    int t = threadIdx.x;
    int bid = blockIdx.x;
    int s = 0;
    for (int j = t; j < bid; j += 256) s += g_bsum[j];
    sh[t] = s;
    __syncthreads();
    for (int off = 128; off > 0; off >>= 1) {
        if (t < off) sh[t] += sh[t + off];
        __syncthreads();
    }
    int off = sh[0];
    int i = bid * 256 + t;
    if (i < NN) {
        int rs = g_rowstart[i] + off;
        g_rowstart[i] = rs;
        g_rowend[i]  += off;
        g_fill[i] = rs;                                // cursor = global start
    }
}

// ---------------------------------------------------------------------------
// Reorder: pos = atomicAdd(fill[d], 1). ONE atomic, no extra loads.
// ---------------------------------------------------------------------------
__global__ void k_reorder(const int* __restrict__ src, const int* __restrict__ dst,
                          const float* __restrict__ w) {
    int t = blockIdx.x * blockDim.x + threadIdx.x;
    int e = t * 4;
    if (e + 4 <= EE) {
        int4 s = *reinterpret_cast<const int4*>(src + e);
        int4 d = *reinterpret_cast<const int4*>(dst + e);
        float4 wv = *reinterpret_cast<const float4*>(w + e);
        float c0 = g_dis[s.x] * wv.x * g_dis[d.x];
        float c1 = g_dis[s.y] * wv.y * g_dis[d.y];
        float c2 = g_dis[s.z] * wv.z * g_dis[d.z];
        float c3 = g_dis[s.w] * wv.w * g_dis[d.w];
        int p0 = atomicAdd(&g_fill[d.x], 1);
        int p1 = atomicAdd(&g_fill[d.y], 1);
        int p2 = atomicAdd(&g_fill[d.z], 1);
        int p3 = atomicAdd(&g_fill[d.w], 1);
        g_epair[p0] = make_int2(s.x << 8, __float_as_int(c0));
        g_epair[p1] = make_int2(s.y << 8, __float_as_int(c1));
        g_epair[p2] = make_int2(s.z << 8, __float_as_int(c2));
        g_epair[p3] = make_int2(s.w << 8, __float_as_int(c3));
    } else {
        for (; e < EE; e++) {
            int sv = src[e];
            int d = dst[e];
            float c = g_dis[sv] * w[e] * g_dis[d];
            int pos = atomicAdd(&g_fill[d], 1);
            g_epair[pos] = make_int2(sv << 8, __float_as_int(c));
        }
    }
}

// ---------------------------------------------------------------------------
// Register-blocked GEMM (R7-proven, 41us): H[n][o] = sum_k X[n][k]*W[o][k]
// ---------------------------------------------------------------------------
__global__ void __launch_bounds__(256) k_gemm(const float* __restrict__ X,
                                              const float* __restrict__ W,
                                              float* __restrict__ H) {
    __shared__ float Xs[128][65];
    __shared__ float Ws[DD][DD];      // Ws[k][o] = W[o][k]

    int tid = threadIdx.x;
    int lane = tid & 31;
    int grp  = tid >> 5;
    int row0 = blockIdx.x * 128;

    for (int idx = tid; idx < (DD * DD) / 4; idx += 256) {
        int o = idx >> 4;
        int k4 = (idx & 15) * 4;
        float4 v = *reinterpret_cast<const float4*>(W + o * DD + k4);
        Ws[k4 + 0][o] = v.x;
        Ws[k4 + 1][o] = v.y;
        Ws[k4 + 2][o] = v.z;
        Ws[k4 + 3][o] = v.w;
    }
    for (int idx = tid; idx < (128 * DD) / 4; idx += 256) {
        int r = idx >> 4;
        int k4 = (idx & 15) * 4;
        int row = row0 + r;
        float4 v = (row < NN) ? *reinterpret_cast<const float4*>(X + (size_t)row * DD + k4)
                              : make_float4(0.f, 0.f, 0.f, 0.f);
        Xs[r][k4 + 0] = v.x;
        Xs[r][k4 + 1] = v.y;
        Xs[r][k4 + 2] = v.z;
        Xs[r][k4 + 3] = v.w;
    }
    __syncthreads();

    int c0 = grp * 8;
    float acc[4][8];
#pragma unroll
    for (int i = 0; i < 4; i++)
#pragma unroll
        for (int j = 0; j < 8; j++) acc[i][j] = 0.0f;

#pragma unroll 4
    for (int k = 0; k < DD; k++) {
        float xv0 = Xs[lane      ][k];
        float xv1 = Xs[lane + 32 ][k];
        float xv2 = Xs[lane + 64 ][k];
        float xv3 = Xs[lane + 96 ][k];
        float4 w0 = *reinterpret_cast<const float4*>(&Ws[k][c0]);
        float4 w1 = *reinterpret_cast<const float4*>(&Ws[k][c0 + 4]);
        float wv[8] = {w0.x, w0.y, w0.z, w0.w, w1.x, w1.y, w1.z, w1.w};
#pragma unroll
        for (int j = 0; j < 8; j++) {
            acc[0][j] = fmaf(xv0, wv[j], acc[0][j]);
            acc[1][j] = fmaf(xv1, wv[j], acc[1][j]);
            acc[2][j] = fmaf(xv2, wv[j], acc[2][j]);
            acc[3][j] = fmaf(xv3, wv[j], acc[3][j]);
        }
    }

#pragma unroll
    for (int i = 0; i < 4; i++) {
        int row = row0 + lane + i * 32;
        if (row < NN) {
            float* hp = H + (size_t)row * DD + c0;
            *reinterpret_cast<float4*>(hp)     = make_float4(acc[i][0], acc[i][1], acc[i][2], acc[i][3]);
            *reinterpret_cast<float4*>(hp + 4) = make_float4(acc[i][4], acc[i][5], acc[i][6], acc[i][7]);
        }
    }
}

// ---------------------------------------------------------------------------
// FUSED gather1+gemm2: 512 threads, 16 warps, ONE warp per node (proven
// lane-split gather), result relu(agg+b1) -> smem, then 16x64 GEMM vs W2.
// ---------------------------------------------------------------------------
__global__ void __launch_bounds__(512) k_gather_gemm(const float* __restrict__ H,
                                                     const float* __restrict__ W2,
                                                     const float* __restrict__ b1,
                                                     float* __restrict__ H2) {
    __shared__ float sW[DD][66];      // sW[k][o], pad 66 (8B-aligned rows)
    __shared__ float sA[16][68];      // relu(agg+b1)

    int tid = threadIdx.x;
    int wid = tid >> 5;               // 0..15 = local node
    int lane = tid & 31;
    int half = lane >> 4;
    unsigned qoff = (unsigned)(lane & 15) * 16u;
    int node0 = blockIdx.x * 16;
    int n = node0 + wid;
    const char* __restrict__ Hb = reinterpret_cast<const char*>(H);

    // stage W2 transposed: sW[k][o] = W2[o][k]  (4096 elems, 8 float4/thread)
    for (int idx = tid; idx < (DD * DD) / 4; idx += 512) {
        int o = idx >> 4;
        int k4 = (idx & 15) * 4;
        float4 v = *reinterpret_cast<const float4*>(W2 + o * DD + k4);
        sW[k4 + 0][o] = v.x;
        sW[k4 + 1][o] = v.y;
        sW[k4 + 2][o] = v.z;
        sW[k4 + 3][o] = v.w;
    }

    // ---- gather phase (identical structure to proven k_gather) ----
    int beg = g_rowstart[n];
    int end = g_rowend[n];

    float4 a0 = make_float4(0.f, 0.f, 0.f, 0.f);
    float4 a1 = a0;

    for (int e = beg; e < end; e += 8) {
        int4 p0 = *reinterpret_cast<const int4*>(&g_epair[e]);
        int4 p1 = *reinterpret_cast<const int4*>(&g_epair[e + 2]);
        int4 p2 = *reinterpret_cast<const int4*>(&g_epair[e + 4]);
        int4 p3 = *reinterpret_cast<const int4*>(&g_epair[e + 6]);

        unsigned o0 = (unsigned)(half ? p0.z : p0.x);
        unsigned o1 = (unsigned)(half ? p1.z : p1.x);
        unsigned o2 = (unsigned)(half ? p2.z : p2.x);
        unsigned o3 = (unsigned)(half ? p3.z : p3.x);

        float4 f0 = *reinterpret_cast<const float4*>(Hb + o0 + qoff);
        float4 f1 = *reinterpret_cast<const float4*>(Hb + o1 + qoff);
        float4 f2 = *reinterpret_cast<const float4*>(Hb + o2 + qoff);
        float4 f3 = *reinterpret_cast<const float4*>(Hb + o3 + qoff);

        float c0 = __int_as_float(half ? p0.w : p0.y);
        float c1 = __int_as_float(half ? p1.w : p1.y);
        float c2 = __int_as_float(half ? p2.w : p2.y);
        float c3 = __int_as_float(half ? p3.w : p3.y);

        a0.x = fmaf(c0, f0.x, a0.x); a0.y = fmaf(c0, f0.y, a0.y);
        a0.z = fmaf(c0, f0.z, a0.z); a0.w = fmaf(c0, f0.w, a0.w);
        a1.x = fmaf(c1, f1.x, a1.x); a1.y = fmaf(c1, f1.y, a1.y);
        a1.z = fmaf(c1, f1.z, a1.z); a1.w = fmaf(c1, f1.w, a1.w);
        a0.x = fmaf(c2, f2.x, a0.x); a0.y = fmaf(c2, f2.y, a0.y);
        a0.z = fmaf(c2, f2.z, a0.z); a0.w = fmaf(c2, f2.w, a0.w);
        a1.x = fmaf(c3, f3.x, a1.x); a1.y = fmaf(c3, f3.y, a1.y);
        a1.z = fmaf(c3, f3.z, a1.z); a1.w = fmaf(c3, f3.w, a1.w);
    }

    float4 a;
    a.x = a0.x + a1.x; a.y = a0.y + a1.y;
    a.z = a0.z + a1.z; a.w = a0.w + a1.w;
    a.x += __shfl_xor_sync(0xffffffffu, a.x, 16);
    a.y += __shfl_xor_sync(0xffffffffu, a.y, 16);
    a.z += __shfl_xor_sync(0xffffffffu, a.z, 16);
    a.w += __shfl_xor_sync(0xffffffffu, a.w, 16);

    float dn = g_dis[n];
    float s2 = dn * dn;
    float4 hs = *reinterpret_cast<const float4*>(Hb + ((unsigned)n << 8) + qoff);
    float4 bv = reinterpret_cast<const float4*>(b1)[lane & 15];

    if (half == 0) {
        float4 r;
        r.x = fmaxf(a.x + hs.x * s2 + bv.x, 0.f);
        r.y = fmaxf(a.y + hs.y * s2 + bv.y, 0.f);
        r.z = fmaxf(a.z + hs.z * s2 + bv.z, 0.f);
        r.w = fmaxf(a.w + hs.w * s2 + bv.w, 0.f);
        *reinterpret_cast<float4*>(&sA[wid][(lane & 15) * 4]) = r;
    }
    __syncthreads();

    // ---- GEMM phase: thread = 1 row x 2 cols ----
    int row = tid >> 5;               // 0..15
    int cb = (tid & 31) * 2;          // 0..62
    float2 acc = make_float2(0.f, 0.f);
#pragma unroll 8
    for (int k = 0; k < DD; k++) {
        float av = sA[row][k];
        float2 wv = *reinterpret_cast<const float2*>(&sW[k][cb]);
        acc.x = fmaf(av, wv.x, acc.x);
        acc.y = fmaf(av, wv.y, acc.y);
    }
    *reinterpret_cast<float2*>(H2 + (size_t)(node0 + row) * DD + cb) = acc;
}

// ---------------------------------------------------------------------------
// Final gather (layer 2): lane-split, padded rows; out = gather(H2)+b2.
// ---------------------------------------------------------------------------
__global__ void __launch_bounds__(256) k_gather(const float* __restrict__ H,
                                                float* __restrict__ OUT,
                                                const float* __restrict__ b,
                                                int do_relu) {
    int n = (blockIdx.x * blockDim.x + threadIdx.x) >> 5;
    if (n >= NN) return;
    int lane = threadIdx.x & 31;
    int half = lane >> 4;
    unsigned qoff = (unsigned)(lane & 15) * 16u;
    const char* __restrict__ Hb = reinterpret_cast<const char*>(H);

    int beg = g_rowstart[n];
    int end = g_rowend[n];

    float4 a0 = make_float4(0.f, 0.f, 0.f, 0.f);
    float4 a1 = a0;

    for (int e = beg; e < end; e += 8) {
        int4 p0 = *reinterpret_cast<const int4*>(&g_epair[e]);
        int4 p1 = *reinterpret_cast<const int4*>(&g_epair[e + 2]);
        int4 p2 = *reinterpret_cast<const int4*>(&g_epair[e + 4]);
        int4 p3 = *reinterpret_cast<const int4*>(&g_epair[e + 6]);

        unsigned o0 = (unsigned)(half ? p0.z : p0.x);
        unsigned o1 = (unsigned)(half ? p1.z : p1.x);
        unsigned o2 = (unsigned)(half ? p2.z : p2.x);
        unsigned o3 = (unsigned)(half ? p3.z : p3.x);

        float4 f0 = *reinterpret_cast<const float4*>(Hb + o0 + qoff);
        float4 f1 = *reinterpret_cast<const float4*>(Hb + o1 + qoff);
        float4 f2 = *reinterpret_cast<const float4*>(Hb + o2 + qoff);
        float4 f3 = *reinterpret_cast<const float4*>(Hb + o3 + qoff);

        float c0 = __int_as_float(half ? p0.w : p0.y);
        float c1 = __int_as_float(half ? p1.w : p1.y);
        float c2 = __int_as_float(half ? p2.w : p2.y);
        float c3 = __int_as_float(half ? p3.w : p3.y);

        a0.x = fmaf(c0, f0.x, a0.x); a0.y = fmaf(c0, f0.y, a0.y);
        a0.z = fmaf(c0, f0.z, a0.z); a0.w = fmaf(c0, f0.w, a0.w);
        a1.x = fmaf(c1, f1.x, a1.x); a1.y = fmaf(c1, f1.y, a1.y);
        a1.z = fmaf(c1, f1.z, a1.z); a1.w = fmaf(c1, f1.w, a1.w);
        a0.x = fmaf(c2, f2.x, a0.x); a0.y = fmaf(c2, f2.y, a0.y);
        a0.z = fmaf(c2, f2.z, a0.z); a0.w = fmaf(c2, f2.w, a0.w);
        a1.x = fmaf(c3, f3.x, a1.x); a1.y = fmaf(c3, f3.y, a1.y);
        a1.z = fmaf(c3, f3.z, a1.z); a1.w = fmaf(c3, f3.w, a1.w);
    }

    float4 a;
    a.x = a0.x + a1.x; a.y = a0.y + a1.y;
    a.z = a0.z + a1.z; a.w = a0.w + a1.w;
    a.x += __shfl_xor_sync(0xffffffffu, a.x, 16);
    a.y += __shfl_xor_sync(0xffffffffu, a.y, 16);
    a.z += __shfl_xor_sync(0xffffffffu, a.z, 16);
    a.w += __shfl_xor_sync(0xffffffffu, a.w, 16);

    float dn = g_dis[n];
    float s2 = dn * dn;
    float4 hs = *reinterpret_cast<const float4*>(Hb + ((unsigned)n << 8) + qoff);
    float4 bv = reinterpret_cast<const float4*>(b)[lane & 15];

    float4 r;
    r.x = a.x + hs.x * s2 + bv.x;
    r.y = a.y + hs.y * s2 + bv.y;
    r.z = a.z + hs.z * s2 + bv.z;
    r.w = a.w + hs.w * s2 + bv.w;
    if (do_relu) {
        r.x = fmaxf(r.x, 0.f); r.y = fmaxf(r.y, 0.f);
        r.z = fmaxf(r.z, 0.f); r.w = fmaxf(r.w, 0.f);
    }
    if (half == 0)
        reinterpret_cast<float4*>(OUT)[((size_t)n << 4) + (lane & 15)] = r;
}

// ---------------------------------------------------------------------------
// Launch: gemm1 forked; build on stream 0; fused gather1+gemm2; gather2.
// ---------------------------------------------------------------------------
extern "C" void kernel_launch(void* const* d_in, const int* in_sizes, int n_in,
                              void* d_out, int out_size) {
    const float* x  = (const float*)d_in[0];
    const int*   ei = (const int*)d_in[1];
    const float* w  = (const float*)d_in[2];
    const float* W1 = (const float*)d_in[3];
    const float* b1 = (const float*)d_in[4];
    const float* W2 = (const float*)d_in[5];
    const float* b2 = (const float*)d_in[6];
    float* out = (float*)d_out;

    const int* src = ei;
    const int* dst = ei + EE;

    float* h_p;   cudaGetSymbolAddress((void**)&h_p,   g_h);
    float* h2_p;  cudaGetSymbolAddress((void**)&h2_p,  g_h2);

    const int T = 256;
    int bE4 = (EE / 4 + T - 1) / T;            // 1221
    int bG  = (NN + 127) / 128;                // 782
    int bW  = (NN * 32 + T - 1) / T;           // 12500 (1 warp/node)
    int bF  = NN / 16;                         // 6250 fused blocks

    cudaStream_t s2;
    cudaStreamCreateWithFlags(&s2, cudaStreamNonBlocking);
    cudaEvent_t evFork, evJoin;
    cudaEventCreateWithFlags(&evFork, cudaEventDisableTiming);
    cudaEventCreateWithFlags(&evJoin, cudaEventDisableTiming);

    // Fork: gemm1 runs concurrent with the CSR build chain.
    cudaEventRecord(evFork, 0);
    cudaStreamWaitEvent(s2, evFork, 0);
    k_gemm<<<bG, T, 0, s2>>>(x, W1, h_p);

    // Build chain on stream 0.
    k_hist<<<bE4, T>>>(dst, w);
    k_scan1<<<NB, 256>>>();
    k_scan3<<<NB, 256>>>();
    k_reorder<<<bE4, T>>>(src, dst, w);

    // Join: fused kernel needs g_h (s2) and the CSR (stream 0).
    cudaEventRecord(evJoin, s2);
    cudaStreamWaitEvent(0, evJoin, 0);

    k_gather_gemm<<<bF, 512>>>(h_p, W2, b1, h2_p);   // fused gather1+gemm2
    k_gather<<<bW, T>>>(h2_p, out, b2, 0);           // final gather
}